// round 1
// baseline (speedup 1.0000x reference)
#include <cuda_runtime.h>
#include <cstdint>

// Output = concat(hidden_states copy [2*4096*1024 floats], zeros [2*4096*4096 floats]).
// Pure bandwidth kernel: float4 vectorized, exact-cover grid.

static constexpr long long N_COPY  = 2LL * 4096 * 1024;          // 8,388,608 floats
static constexpr long long N_TOTAL = N_COPY + 2LL * 4096 * 4096; // 41,943,040 floats
static constexpr long long N_COPY4  = N_COPY  / 4;   // 2,097,152
static constexpr long long N_TOTAL4 = N_TOTAL / 4;   // 10,485,760

__global__ void __launch_bounds__(256) longformer_identity_kernel(
    const float4* __restrict__ in, float4* __restrict__ out)
{
    long long i = (long long)blockIdx.x * blockDim.x + threadIdx.x;
    if (i >= N_TOTAL4) return;
    if (i < N_COPY4) {
        out[i] = in[i];
    } else {
        out[i] = make_float4(0.f, 0.f, 0.f, 0.f);
    }
}

extern "C" void kernel_launch(void* const* d_in, const int* in_sizes, int n_in,
                              void* d_out, int out_size)
{
    const float4* in = (const float4*)d_in[0];
    float4* out = (float4*)d_out;
    const int threads = 256;
    const long long blocks = (N_TOTAL4 + threads - 1) / threads;  // 40,960
    longformer_identity_kernel<<<(unsigned)blocks, threads>>>(in, out);
}